// round 1
// baseline (speedup 1.0000x reference)
#include <cuda_runtime.h>

// Bilinear_3882650435896: conv_transpose2d(x, w, stride=2), w block-diagonal
// (per-channel bilinear upsample filter). Exploit diagonality: depthwise
// 2x upsample. x: (4,256,128,128) f32 -> out: (4,256,258,258) f32.
//
// Each thread computes one 2x2 output block at (2r, 2s), r,s in [0,129).
// The 4 outputs share 4 input taps x[r-1..r][s-1..s] (zero-padded at edges).

#define C        256
#define HIN      128
#define HOUT     258
#define RS       129           // output 2x2-blocks per dimension (258/2)
#define PIX      (RS * RS)     // 16641 blocks per (n,c) image

__global__ void __launch_bounds__(256)
bilinear_up_kernel(const float* __restrict__ x,
                   const float* __restrict__ w,
                   float* __restrict__ out)
{
    const int nc = blockIdx.y;          // n*C + c, 0..1023
    const int c  = nc & (C - 1);

    // Stage the 16 diagonal filter taps f[kh*4+kw] = w[c][c][kh][kw].
    __shared__ float f[16];
    if (threadIdx.x < 16)
        f[threadIdx.x] = w[(size_t)c * (C + 1) * 16 + threadIdx.x];
    __syncthreads();

    const int idx = blockIdx.x * blockDim.x + threadIdx.x;
    if (idx >= PIX) return;
    const int r = idx / RS;
    const int s = idx - r * RS;

    const float* __restrict__ xin = x + (size_t)nc * (HIN * HIN);

    const bool rv = (r < HIN), rm = (r >= 1);
    const bool sv = (s < HIN), sm = (s >= 1);

    float x00 = 0.f, x01 = 0.f, x10 = 0.f, x11 = 0.f;
    if (rm && sm) x00 = __ldg(&xin[(r - 1) * HIN + (s - 1)]);
    if (rm && sv) x01 = __ldg(&xin[(r - 1) * HIN + s]);
    if (rv && sm) x10 = __ldg(&xin[r * HIN + (s - 1)]);
    if (rv && sv) x11 = __ldg(&xin[r * HIN + s]);

    // out[2r  ][2s  ] : (ih=r,kh=0)(ih=r-1,kh=2) x (iw=s,kw=0)(iw=s-1,kw=2)
    // out[2r  ][2s+1] : kw = 1 / 3
    // out[2r+1][2s  ] : kh = 1 / 3
    // out[2r+1][2s+1] : both odd
    const float o00 = x11 * f[0]  + x10 * f[2]  + x01 * f[8]  + x00 * f[10];
    const float o01 = x11 * f[1]  + x10 * f[3]  + x01 * f[9]  + x00 * f[11];
    const float o10 = x11 * f[4]  + x10 * f[6]  + x01 * f[12] + x00 * f[14];
    const float o11 = x11 * f[5]  + x10 * f[7]  + x01 * f[13] + x00 * f[15];

    float* __restrict__ orow =
        out + (size_t)nc * (HOUT * HOUT) + (size_t)(2 * r) * HOUT + 2 * s;
    // Row stride 258*4 = 1032 B (8-aligned), col offset 8s B -> float2 OK.
    *reinterpret_cast<float2*>(orow)        = make_float2(o00, o01);
    *reinterpret_cast<float2*>(orow + HOUT) = make_float2(o10, o11);
}

extern "C" void kernel_launch(void* const* d_in, const int* in_sizes, int n_in,
                              void* d_out, int out_size)
{
    const float* x = (const float*)d_in[0];   // (4,256,128,128)
    const float* w = (const float*)d_in[1];   // (256,256,4,4)
    float* out = (float*)d_out;               // (4,256,258,258)

    const int nimg = 4 * C;                   // 1024 (n,c) planes
    dim3 block(256);
    dim3 grid((PIX + 255) / 256, nimg);       // (66, 1024)
    bilinear_up_kernel<<<grid, block>>>(x, w, out);
}

// round 2
// speedup vs baseline: 1.2895x; 1.2895x over previous
#include <cuda_runtime.h>

// Bilinear_3882650435896: conv_transpose2d(x, w, stride=2) with block-diagonal
// w (per-channel bilinear filter) == depthwise 2x upsample.
// x: (4,256,128,128) f32 -> out: (4,256,258,258) f32.
//
// R1 -> R2: warp-per-output-row-pair mapping. Each warp handles row pair
// (2r, 2r+1); lanes sweep columns in 4 chunks of 32 (s = lane + 32k) plus a
// lane-0 tail at s=128. Loads front-batched (MLP=16/thread), stores contiguous
// per warp per chunk, streaming (evict-first) since output is never re-read.

#define C     256
#define HIN   128
#define HOUT  258

__global__ void __launch_bounds__(256)
bilinear_up_kernel(const float* __restrict__ x,
                   const float* __restrict__ w,
                   float* __restrict__ out)
{
    const int nc = blockIdx.y;            // n*C + c, 0..1023
    const int c  = nc & (C - 1);

    __shared__ float fs[16];
    if (threadIdx.x < 16)
        fs[threadIdx.x] = w[(size_t)c * (C + 1) * 16 + threadIdx.x];
    __syncthreads();

    // Filter taps into registers (uniform per block).
    float f0 = fs[0],  f1 = fs[1],  f2 = fs[2],  f3 = fs[3];
    float f4 = fs[4],  f5 = fs[5],  f6 = fs[6],  f7 = fs[7];
    float f8 = fs[8],  f9 = fs[9],  f10 = fs[10], f11 = fs[11];
    float f12 = fs[12], f13 = fs[13], f14 = fs[14], f15 = fs[15];

    const int warp = threadIdx.x >> 5;
    const int lane = threadIdx.x & 31;
    const int r    = blockIdx.x * 8 + warp;   // output row-pair index, 0..128
    if (r > HIN) return;                      // r in [0,128]

    const float* __restrict__ xin = x + (size_t)nc * (HIN * HIN);
    const float* __restrict__ xr0 = xin + (size_t)(r - 1) * HIN; // row r-1
    const float* __restrict__ xr1 = xin + (size_t)r * HIN;       // row r
    const bool rm = (r >= 1);
    const bool rv = (r < HIN);

    float* __restrict__ o0 =
        out + (size_t)nc * (HOUT * HOUT) + (size_t)(2 * r) * HOUT;
    float* __restrict__ o1 = o0 + HOUT;

    // Front-batched loads: 4 chunks x 4 taps. For k<4, s = lane+32k <= 127,
    // so the s-tap is always in-range; only s-1 needs the s>=1 predicate.
    float a00[4], a01[4], a10[4], a11[4];
#pragma unroll
    for (int k = 0; k < 4; k++) {
        const int s = lane + 32 * k;
        const bool sm = (s >= 1);
        a00[k] = (rm && sm) ? __ldg(&xr0[s - 1]) : 0.f;
        a01[k] = rm         ? __ldg(&xr0[s])     : 0.f;
        a10[k] = (rv && sm) ? __ldg(&xr1[s - 1]) : 0.f;
        a11[k] = rv         ? __ldg(&xr1[s])     : 0.f;
    }

#pragma unroll
    for (int k = 0; k < 4; k++) {
        const int s = lane + 32 * k;
        const float x00 = a00[k], x01 = a01[k], x10 = a10[k], x11 = a11[k];
        const float v00 = x11 * f0 + x10 * f2  + x01 * f8  + x00 * f10;
        const float v01 = x11 * f1 + x10 * f3  + x01 * f9  + x00 * f11;
        const float v10 = x11 * f4 + x10 * f6  + x01 * f12 + x00 * f14;
        const float v11 = x11 * f5 + x10 * f7  + x01 * f13 + x00 * f15;
        __stcs(reinterpret_cast<float2*>(o0 + 2 * s), make_float2(v00, v01));
        __stcs(reinterpret_cast<float2*>(o1 + 2 * s), make_float2(v10, v11));
    }

    // Tail column group: s = 128 (output cols 256,257). Only the s-1 taps
    // (input col 127) contribute; x[.][128] is out of range.
    if (lane == 0) {
        const float x00 = rm ? __ldg(&xr0[HIN - 1]) : 0.f;
        const float x10 = rv ? __ldg(&xr1[HIN - 1]) : 0.f;
        const float v00 = x10 * f2  + x00 * f10;
        const float v01 = x10 * f3  + x00 * f11;
        const float v10 = x10 * f6  + x00 * f14;
        const float v11 = x10 * f7  + x00 * f15;
        __stcs(reinterpret_cast<float2*>(o0 + 2 * HIN), make_float2(v00, v01));
        __stcs(reinterpret_cast<float2*>(o1 + 2 * HIN), make_float2(v10, v11));
    }
}

extern "C" void kernel_launch(void* const* d_in, const int* in_sizes, int n_in,
                              void* d_out, int out_size)
{
    const float* x = (const float*)d_in[0];   // (4,256,128,128)
    const float* w = (const float*)d_in[1];   // (256,256,4,4)
    float* out = (float*)d_out;               // (4,256,258,258)

    // 129 row-pairs per image, 8 warps per block -> 17 blocks in x.
    dim3 block(256);
    dim3 grid((HIN + 1 + 7) / 8, 4 * C);      // (17, 1024)
    bilinear_up_kernel<<<grid, block>>>(x, w, out);
}